// round 2
// baseline (speedup 1.0000x reference)
#include <cuda_runtime.h>
#include <cstdint>
#include <math.h>

#define BB 64
#define TT 512
#define DD 512
#define UU 1024
#define G4 4096   // 4*UU

// Scratch (allocation-free rule: __device__ globals)
__device__ float g_xg[(size_t)TT * BB * G4];   // [T][B][4U]  512 MB
__device__ float g_h[2 * BB * UU];             // ping-pong h
__device__ float g_c[BB * UU];                 // cell state (owner-exclusive)

// ---------- helpers ----------
__device__ __forceinline__ unsigned f2tf(float x) {
    unsigned r;
    asm volatile("cvt.rna.tf32.f32 %0, %1;" : "=r"(r) : "f"(x));
    return r;
}
__device__ __forceinline__ float tfbits(float x) { return __uint_as_float(f2tf(x)); }
__device__ __forceinline__ unsigned fu(float x) { return __float_as_uint(x); }

__device__ __forceinline__ void mma_tf32(float d[4], const unsigned a[4], unsigned b0, unsigned b1) {
    asm volatile(
        "mma.sync.aligned.m16n8k8.row.col.f32.tf32.tf32.f32 "
        "{%0,%1,%2,%3}, {%4,%5,%6,%7}, {%8,%9}, {%0,%1,%2,%3};"
        : "+f"(d[0]), "+f"(d[1]), "+f"(d[2]), "+f"(d[3])
        : "r"(a[0]), "r"(a[1]), "r"(a[2]), "r"(a[3]), "r"(b0), "r"(b1));
}

__device__ __forceinline__ float sigmoidf_(float z) { return 1.f / (1.f + expf(-z)); }

// ---------- Kernel 1: xg = x @ Wx + b, written as [T][B][4U] ----------
// BM=64, BN=64, BK=32, 128 threads (4 warps, 2x2 warp grid, each warp 32x32 = 2x4 m16n8 tiles)
__global__ void __launch_bounds__(128) xg_kernel(const float* __restrict__ x,
                                                 const float* __restrict__ Wx,
                                                 const float* __restrict__ bias) {
    __shared__ float As[64][33];
    __shared__ float Bs[32][65];

    const int tid  = threadIdx.x;
    const int w    = tid >> 5;
    const int lane = tid & 31;
    const int gid  = lane >> 2;   // 0..7
    const int tig  = lane & 3;    // 0..3
    const int wm   = w >> 1;      // 0..1  rows base wm*32
    const int wn   = w & 1;       // 0..1  cols base wn*32

    const int m0 = blockIdx.y * 64;
    const int c0 = blockIdx.x * 64;

    float acc[2][4][4];
#pragma unroll
    for (int mi = 0; mi < 2; mi++)
#pragma unroll
        for (int ni = 0; ni < 4; ni++)
#pragma unroll
            for (int j = 0; j < 4; j++) acc[mi][ni][j] = 0.f;

    for (int kc = 0; kc < DD; kc += 32) {
        // load A tile: 64 rows x 32 k  (x row m is linear: m*DD)
#pragma unroll
        for (int i = 0; i < 4; i++) {
            int id  = tid + i * 128;          // 0..511 float4s
            int row = id >> 3;
            int k4  = (id & 7) * 4;
            float4 v = *reinterpret_cast<const float4*>(x + (size_t)(m0 + row) * DD + kc + k4);
            As[row][k4 + 0] = tfbits(v.x);
            As[row][k4 + 1] = tfbits(v.y);
            As[row][k4 + 2] = tfbits(v.z);
            As[row][k4 + 3] = tfbits(v.w);
        }
        // load B tile: 32 k x 64 cols
#pragma unroll
        for (int i = 0; i < 4; i++) {
            int id = tid + i * 128;           // 0..511 float4s
            int k  = id >> 4;
            int n4 = (id & 15) * 4;
            float4 v = *reinterpret_cast<const float4*>(Wx + (size_t)(kc + k) * G4 + c0 + n4);
            Bs[k][n4 + 0] = tfbits(v.x);
            Bs[k][n4 + 1] = tfbits(v.y);
            Bs[k][n4 + 2] = tfbits(v.z);
            Bs[k][n4 + 3] = tfbits(v.w);
        }
        __syncthreads();

#pragma unroll
        for (int q = 0; q < 4; q++) {
            const int kk = q * 8 + tig;
            unsigned a[2][4];
#pragma unroll
            for (int mi = 0; mi < 2; mi++) {
                int r0 = wm * 32 + mi * 16 + gid;
                a[mi][0] = fu(As[r0][kk]);
                a[mi][1] = fu(As[r0 + 8][kk]);
                a[mi][2] = fu(As[r0][kk + 4]);
                a[mi][3] = fu(As[r0 + 8][kk + 4]);
            }
#pragma unroll
            for (int ni = 0; ni < 4; ni++) {
                int cb = wn * 32 + ni * 8 + gid;
                unsigned b0 = fu(Bs[kk][cb]);
                unsigned b1 = fu(Bs[kk + 4][cb]);
#pragma unroll
                for (int mi = 0; mi < 2; mi++) mma_tf32(acc[mi][ni], a[mi], b0, b1);
            }
        }
        __syncthreads();
    }

    // epilogue: add bias, scatter to g_xg[t][b][col]
#pragma unroll
    for (int mi = 0; mi < 2; mi++) {
#pragma unroll
        for (int ni = 0; ni < 4; ni++) {
#pragma unroll
            for (int j = 0; j < 4; j++) {
                int m   = m0 + wm * 32 + mi * 16 + gid + ((j >= 2) ? 8 : 0);
                int col = c0 + wn * 32 + ni * 8 + tig * 2 + (j & 1);
                float v = acc[mi][ni][j] + bias[col];
                int bidx = m >> 9;       // m / TT
                int tidx = m & (TT - 1); // m % TT
                g_xg[(size_t)tidx * (BB * G4) + (size_t)bidx * G4 + col] = v;
            }
        }
    }
}

// ---------- Kernel 2: one LSTM step (fused GEMM + gates) ----------
// Block: 16 u-columns across all 4 gate segments; all 64 batch rows.
// 256 threads = 8 warps: wm = w&3 -> row tile (16 rows), wn = w>>2 -> u half (8 cols).
// Each warp: 4 gate accumulators (m16n8 each). K = 1024, BK = 32.
__global__ void __launch_bounds__(256) lstm_step(const float* __restrict__ Wh,
                                                 int t,
                                                 const float* __restrict__ h_in,
                                                 float* __restrict__ h_out) {
    __shared__ float hs[64][33];
    __shared__ float Ws[32][65];

    const int tid  = threadIdx.x;
    const int w    = tid >> 5;
    const int lane = tid & 31;
    const int gid  = lane >> 2;
    const int tig  = lane & 3;
    const int wm   = w & 3;     // row tile: rows wm*16..+15
    const int wn   = w >> 2;    // 0..1: u cols wn*8..+7 within the 16-wide tile
    const int u0   = blockIdx.x * 16;

    float acc[4][4];
#pragma unroll
    for (int g = 0; g < 4; g++)
#pragma unroll
        for (int j = 0; j < 4; j++) acc[g][j] = 0.f;

    for (int kc = 0; kc < UU; kc += 32) {
        // h tile: 64 rows x 32 k
#pragma unroll
        for (int i = 0; i < 2; i++) {
            int id  = tid + i * 256;        // 0..511 float4s
            int row = id >> 3;
            int k4  = (id & 7) * 4;
            float4 v = *reinterpret_cast<const float4*>(h_in + (size_t)row * UU + kc + k4);
            hs[row][k4 + 0] = tfbits(v.x);
            hs[row][k4 + 1] = tfbits(v.y);
            hs[row][k4 + 2] = tfbits(v.z);
            hs[row][k4 + 3] = tfbits(v.w);
        }
        // Wh tile: 32 k x (4 gates x 16 u)
#pragma unroll
        for (int i = 0; i < 2; i++) {
            int id  = tid + i * 256;        // 0..511 float4s
            int k   = id >> 4;
            int sub = id & 15;
            int g   = sub >> 2;
            int n4  = (sub & 3) * 4;
            float4 v = *reinterpret_cast<const float4*>(Wh + (size_t)(kc + k) * G4 + g * UU + u0 + n4);
            Ws[k][g * 16 + n4 + 0] = tfbits(v.x);
            Ws[k][g * 16 + n4 + 1] = tfbits(v.y);
            Ws[k][g * 16 + n4 + 2] = tfbits(v.z);
            Ws[k][g * 16 + n4 + 3] = tfbits(v.w);
        }
        __syncthreads();

#pragma unroll
        for (int q = 0; q < 4; q++) {
            const int kk = q * 8 + tig;
            const int r0 = wm * 16 + gid;
            unsigned a[4];
            a[0] = fu(hs[r0][kk]);
            a[1] = fu(hs[r0 + 8][kk]);
            a[2] = fu(hs[r0][kk + 4]);
            a[3] = fu(hs[r0 + 8][kk + 4]);
#pragma unroll
            for (int g = 0; g < 4; g++) {
                int cb = g * 16 + wn * 8 + gid;
                unsigned b0 = fu(Ws[kk][cb]);
                unsigned b1 = fu(Ws[kk + 4][cb]);
                mma_tf32(acc[g], a, b0, b1);
            }
        }
        __syncthreads();
    }

    // epilogue: gates -> c,h update
    const float* xgt = g_xg + (size_t)t * (BB * G4);
    const int r[2]  = {wm * 16 + gid, wm * 16 + gid + 8};
    const int uc[2] = {u0 + wn * 8 + tig * 2, u0 + wn * 8 + tig * 2 + 1};

#pragma unroll
    for (int jr = 0; jr < 2; jr++) {
#pragma unroll
        for (int jc = 0; jc < 2; jc++) {
            const int j   = jr * 2 + jc;
            const int row = r[jr];
            const int u   = uc[jc];
            const size_t base = (size_t)row * G4;
            float zi = acc[0][j] + xgt[base + 0 * UU + u];
            float zf = acc[1][j] + xgt[base + 1 * UU + u];
            float zg = acc[2][j] + xgt[base + 2 * UU + u];
            float zo = acc[3][j] + xgt[base + 3 * UU + u];

            float ig = sigmoidf_(zi);
            float fg = sigmoidf_(zf);
            float gg = tanhf(zg);
            float og = sigmoidf_(zo);

            const int ci = row * UU + u;
            float cn = fg * g_c[ci] + ig * gg;
            g_c[ci] = cn;
            h_out[ci] = og * tanhf(cn);
        }
    }
}

// ---------- launch ----------
extern "C" void kernel_launch(void* const* d_in, const int* in_sizes, int n_in,
                              void* d_out, int out_size) {
    const float *x = nullptr, *h0 = nullptr, *c0 = nullptr;
    const float *Wx = nullptr, *Wh = nullptr, *bias = nullptr;
    for (int i = 0; i < n_in; i++) {
        const int s = in_sizes[i];
        const float* p = (const float*)d_in[i];
        if      (s == BB * TT * DD) x = p;
        else if (s == DD * G4)      Wx = p;
        else if (s == UU * G4)      Wh = p;
        else if (s == G4)           bias = p;
        else if (s == BB * UU)      { if (!h0) h0 = p; else c0 = p; }
    }

    float* hbuf = nullptr;
    float* cbuf = nullptr;
    cudaGetSymbolAddress((void**)&hbuf, g_h);
    cudaGetSymbolAddress((void**)&cbuf, g_c);

    cudaMemcpyAsync(hbuf, h0, (size_t)BB * UU * sizeof(float), cudaMemcpyDeviceToDevice, 0);
    cudaMemcpyAsync(cbuf, c0, (size_t)BB * UU * sizeof(float), cudaMemcpyDeviceToDevice, 0);

    // xg precompute: grid (4096/64, 32768/64)
    xg_kernel<<<dim3(G4 / 64, (BB * TT) / 64), 128>>>(x, Wx, bias);

    // 512 sequential steps, h ping-pong
    for (int t = 0; t < TT; t++) {
        const float* hin = hbuf + (size_t)(t & 1) * BB * UU;
        float* hout      = hbuf + (size_t)((t + 1) & 1) * BB * UU;
        lstm_step<<<UU / 16, 256>>>(Wh, t, hin, hout);
    }

    // final h is in buffer (TT & 1) == 0
    cudaMemcpyAsync(d_out, hbuf, (size_t)BB * UU * sizeof(float), cudaMemcpyDeviceToDevice, 0);
}

// round 3
// speedup vs baseline: 3.0194x; 3.0194x over previous
#include <cuda_runtime.h>
#include <cstdint>
#include <math.h>

#define BB 64
#define TT 512
#define DD 512
#define UU 1024
#define G4 4096   // 4*UU
#define NBLK 128
#define NTHR 256

// Scratch (allocation-free rule: __device__ globals)
__device__ float g_xg[(size_t)TT * NBLK * BB * 32 / 32 * 32];  // [T][blk][row][g*8+j] = TT*128*64*32 = 512MB
__device__ float g_h[2 * BB * UU];                             // ping-pong h (tf32-rounded except final)
__device__ unsigned g_bar_count;
__device__ volatile unsigned g_bar_gen;

// ---------- helpers ----------
__device__ __forceinline__ unsigned f2tf(float x) {
    unsigned r;
    asm volatile("cvt.rna.tf32.f32 %0, %1;" : "=r"(r) : "f"(x));
    return r;
}
__device__ __forceinline__ float tfbits(float x) { return __uint_as_float(f2tf(x)); }
__device__ __forceinline__ unsigned fu(float x) { return __float_as_uint(x); }

__device__ __forceinline__ void mma_tf32(float d[4], const unsigned a[4], unsigned b0, unsigned b1) {
    asm volatile(
        "mma.sync.aligned.m16n8k8.row.col.f32.tf32.tf32.f32 "
        "{%0,%1,%2,%3}, {%4,%5,%6,%7}, {%8,%9}, {%0,%1,%2,%3};"
        : "+f"(d[0]), "+f"(d[1]), "+f"(d[2]), "+f"(d[3])
        : "r"(a[0]), "r"(a[1]), "r"(a[2]), "r"(a[3]), "r"(b0), "r"(b1));
}
__device__ __forceinline__ float sigmoidf_(float z) { return 1.f / (1.f + expf(-z)); }

__device__ __forceinline__ void cp_async16(uint32_t s, const float* g) {
    asm volatile("cp.async.cg.shared.global [%0], [%1], 16;\n" :: "r"(s), "l"(g));
}
#define CP_COMMIT() asm volatile("cp.async.commit_group;\n" ::: "memory")
#define CP_WAIT(N)  asm volatile("cp.async.wait_group %0;\n" :: "n"(N) : "memory")

// ---------- Kernel 1: xg = x @ Wx + b, relayout to [t][blk][row][g*8+j] ----------
__global__ void __launch_bounds__(128) xg_kernel(const float* __restrict__ x,
                                                 const float* __restrict__ Wx,
                                                 const float* __restrict__ bias) {
    __shared__ float As[64][33];
    __shared__ float Bs[32][65];

    const int tid  = threadIdx.x;
    const int w    = tid >> 5;
    const int lane = tid & 31;
    const int gid  = lane >> 2;
    const int tig  = lane & 3;
    const int wm   = w >> 1;
    const int wn   = w & 1;

    const int m0 = blockIdx.y * 64;
    const int c0 = blockIdx.x * 64;

    float acc[2][4][4];
#pragma unroll
    for (int mi = 0; mi < 2; mi++)
#pragma unroll
        for (int ni = 0; ni < 4; ni++)
#pragma unroll
            for (int j = 0; j < 4; j++) acc[mi][ni][j] = 0.f;

    for (int kc = 0; kc < DD; kc += 32) {
#pragma unroll
        for (int i = 0; i < 4; i++) {
            int id  = tid + i * 128;
            int row = id >> 3;
            int k4  = (id & 7) * 4;
            float4 v = *reinterpret_cast<const float4*>(x + (size_t)(m0 + row) * DD + kc + k4);
            As[row][k4 + 0] = tfbits(v.x);
            As[row][k4 + 1] = tfbits(v.y);
            As[row][k4 + 2] = tfbits(v.z);
            As[row][k4 + 3] = tfbits(v.w);
        }
#pragma unroll
        for (int i = 0; i < 4; i++) {
            int id = tid + i * 128;
            int k  = id >> 4;
            int n4 = (id & 15) * 4;
            float4 v = *reinterpret_cast<const float4*>(Wx + (size_t)(kc + k) * G4 + c0 + n4);
            Bs[k][n4 + 0] = tfbits(v.x);
            Bs[k][n4 + 1] = tfbits(v.y);
            Bs[k][n4 + 2] = tfbits(v.z);
            Bs[k][n4 + 3] = tfbits(v.w);
        }
        __syncthreads();

#pragma unroll
        for (int q = 0; q < 4; q++) {
            const int kk = q * 8 + tig;
            unsigned a[2][4];
#pragma unroll
            for (int mi = 0; mi < 2; mi++) {
                int r0 = wm * 32 + mi * 16 + gid;
                a[mi][0] = fu(As[r0][kk]);
                a[mi][1] = fu(As[r0 + 8][kk]);
                a[mi][2] = fu(As[r0][kk + 4]);
                a[mi][3] = fu(As[r0 + 8][kk + 4]);
            }
#pragma unroll
            for (int ni = 0; ni < 4; ni++) {
                int cb = wn * 32 + ni * 8 + gid;
                unsigned b0 = fu(Bs[kk][cb]);
                unsigned b1 = fu(Bs[kk + 4][cb]);
#pragma unroll
                for (int mi = 0; mi < 2; mi++) mma_tf32(acc[mi][ni], a[mi], b0, b1);
            }
        }
        __syncthreads();
    }

#pragma unroll
    for (int mi = 0; mi < 2; mi++) {
#pragma unroll
        for (int ni = 0; ni < 4; ni++) {
#pragma unroll
            for (int j = 0; j < 4; j++) {
                int m   = m0 + wm * 32 + mi * 16 + gid + ((j >= 2) ? 8 : 0);
                int col = c0 + wn * 32 + ni * 8 + tig * 2 + (j & 1);
                float v = acc[mi][ni][j] + bias[col];
                int b   = m >> 9;        // batch
                int t   = m & (TT - 1);  // time
                int g   = col >> 10;
                int u   = col & (UU - 1);
                int blk = u >> 3;
                int jj  = u & 7;
                g_xg[(((size_t)t * NBLK + blk) * BB + b) * 32 + g * 8 + jj] = v;
            }
        }
    }
}

// ---------- init: h0 -> g_h buffer0 with tf32 rounding ----------
__global__ void init_h(const float* __restrict__ h0) {
    int i = blockIdx.x * blockDim.x + threadIdx.x;
    if (i < BB * UU) g_h[i] = tfbits(h0[i]);
}

// ---------- persistent LSTM kernel ----------
// 128 blocks x 256 threads, 1 block/SM (smem-forced). Block owns u-cols u0..u0+7,
// all 4 gates (32 gate-cols), all 64 rows. Wh slice resident in SMEM as tf32
// pre-swizzled mma B-fragments. c in registers. h ping-pong via global + cp.async.
__global__ void __launch_bounds__(NTHR, 1) lstm_persistent(const float* __restrict__ Wh,
                                                           const float* __restrict__ c0) {
    extern __shared__ float smem[];
    float* FB = smem;                 // 32768 floats: B-fragments [kcc32][tile][lane][8]
    float* HS = FB + 32768;           // 2 * 64*68 floats: h staging, dbl-buffered
    float* GM = HS + 2 * 64 * 68;     // 64*33 floats: gate exchange

    const int tid  = threadIdx.x;
    const int w    = tid >> 5;
    const int lane = tid & 31;
    const int gid  = lane >> 2;
    const int tig  = lane & 3;
    const int wm   = w & 3;           // row tile (16 rows)
    const int wn   = w >> 2;          // tile pair {2wn, 2wn+1}
    const int blk  = blockIdx.x;
    const int u0   = blk * 8;

    // ---- one-time: fill Wh fragments (tf32, pre-swizzled) ----
    // FB[((kcc32*4 + tile)*32 + lane)*8 + q*2 + pair] = tf32(Wh[k][col])
    //   k = kcc32*32 + q*8 + tig + pair*4,  col = tile*1024 + u0 + gid
    for (int idx = tid; idx < 32768; idx += NTHR) {
        int e     = idx & 7;
        int ln    = (idx >> 3) & 31;
        int tile  = (idx >> 8) & 3;
        int kcc32 = idx >> 10;
        int q     = e >> 1;
        int pair  = e & 1;
        int lgid  = ln >> 2;
        int ltig  = ln & 3;
        int k     = kcc32 * 32 + q * 8 + ltig + pair * 4;
        FB[idx] = tfbits(Wh[(size_t)k * G4 + tile * UU + u0 + lgid]);
    }

    // ---- c in registers: thread owns elements e = tid, tid+256 ----
    float creg[2];
#pragma unroll
    for (int i = 0; i < 2; i++) {
        int e = tid + i * NTHR;
        int row = e >> 3, j = e & 7;
        creg[i] = c0[(size_t)row * UU + u0 + j];
    }
    __syncthreads();

    const float4* FB4 = reinterpret_cast<const float4*>(FB);
    const uint32_t hs_base = (uint32_t)__cvta_generic_to_shared(HS);
    const int r0 = wm * 16 + gid;
    const int t0i = wn * 2, t1i = wn * 2 + 1;

    for (int t = 0; t < TT; t++) {
        const float* h_in = g_h + (size_t)(t & 1) * BB * UU;
        float* h_out      = g_h + (size_t)((t + 1) & 1) * BB * UU;

        float acc0[4] = {0.f, 0.f, 0.f, 0.f};
        float acc1[4] = {0.f, 0.f, 0.f, 0.f};

        // prologue: stage chunk 0
#pragma unroll
        for (int i = 0; i < 4; i++) {
            int id = tid + i * NTHR;           // 0..1023 float4s
            int row = id >> 4, kq = id & 15;
            cp_async16(hs_base + (uint32_t)((row * 68 + kq * 4) * 4),
                       h_in + (size_t)row * UU + kq * 4);
        }
        CP_COMMIT();

        for (int kcc = 0; kcc < 16; kcc++) {
            if (kcc + 1 < 16) {
                int buf = (kcc + 1) & 1;
#pragma unroll
                for (int i = 0; i < 4; i++) {
                    int id = tid + i * NTHR;
                    int row = id >> 4, kq = id & 15;
                    cp_async16(hs_base + (uint32_t)((buf * 4352 + row * 68 + kq * 4) * 4),
                               h_in + (size_t)row * UU + (kcc + 1) * 64 + kq * 4);
                }
                CP_COMMIT();
                CP_WAIT(1);
            } else {
                CP_WAIT(0);
            }
            __syncthreads();

            const float* hb = HS + (kcc & 1) * 4352;
#pragma unroll
            for (int sub = 0; sub < 2; sub++) {
                const int kcc32 = kcc * 2 + sub;
                float4 bA0 = FB4[((kcc32 * 4 + t0i) * 32 + lane) * 2 + 0];
                float4 bA1 = FB4[((kcc32 * 4 + t0i) * 32 + lane) * 2 + 1];
                float4 bB0 = FB4[((kcc32 * 4 + t1i) * 32 + lane) * 2 + 0];
                float4 bB1 = FB4[((kcc32 * 4 + t1i) * 32 + lane) * 2 + 1];
#pragma unroll
                for (int q = 0; q < 4; q++) {
                    const int kk = sub * 32 + q * 8 + tig;
                    unsigned a[4];
                    a[0] = fu(hb[r0 * 68 + kk]);
                    a[1] = fu(hb[(r0 + 8) * 68 + kk]);
                    a[2] = fu(hb[r0 * 68 + kk + 4]);
                    a[3] = fu(hb[(r0 + 8) * 68 + kk + 4]);
                    unsigned b0a, b1a, b0b, b1b;
                    if (q == 0)      { b0a = fu(bA0.x); b1a = fu(bA0.y); b0b = fu(bB0.x); b1b = fu(bB0.y); }
                    else if (q == 1) { b0a = fu(bA0.z); b1a = fu(bA0.w); b0b = fu(bB0.z); b1b = fu(bB0.w); }
                    else if (q == 2) { b0a = fu(bA1.x); b1a = fu(bA1.y); b0b = fu(bB1.x); b1b = fu(bB1.y); }
                    else             { b0a = fu(bA1.z); b1a = fu(bA1.w); b0b = fu(bB1.z); b1b = fu(bB1.w); }
                    mma_tf32(acc0, a, b0a, b1a);
                    mma_tf32(acc1, a, b0b, b1b);
                }
            }
            __syncthreads();
        }

        // gate exchange: acc -> GM[row][tile*8 + tig*2 + (j&1)]
#pragma unroll
        for (int j = 0; j < 4; j++) {
            int row = wm * 16 + gid + ((j >> 1) ? 8 : 0);
            int cA  = t0i * 8 + tig * 2 + (j & 1);
            int cB  = t1i * 8 + tig * 2 + (j & 1);
            GM[row * 33 + cA] = acc0[j];
            GM[row * 33 + cB] = acc1[j];
        }
        __syncthreads();

        // epilogue: gates + c/h update (512 elems, 2 per thread)
        const float* xgt = g_xg + ((size_t)t * NBLK + blk) * (BB * 32);
#pragma unroll
        for (int i = 0; i < 2; i++) {
            int e = tid + i * NTHR;
            int row = e >> 3, j = e & 7;
            float zi = GM[row * 33 + 0 * 8 + j] + xgt[row * 32 + 0 * 8 + j];
            float zf = GM[row * 33 + 1 * 8 + j] + xgt[row * 32 + 1 * 8 + j];
            float zg = GM[row * 33 + 2 * 8 + j] + xgt[row * 32 + 2 * 8 + j];
            float zo = GM[row * 33 + 3 * 8 + j] + xgt[row * 32 + 3 * 8 + j];

            float ig = sigmoidf_(zi);
            float fg = sigmoidf_(zf);
            float gg = tanhf(zg);
            float og = sigmoidf_(zo);

            creg[i] = fg * creg[i] + ig * gg;
            float hv = og * tanhf(creg[i]);
            h_out[(size_t)row * UU + u0 + j] = (t == TT - 1) ? hv : tfbits(hv);
        }

        // ---- grid barrier (sense via monotonically increasing gen, reset per launch) ----
        __syncthreads();
        if (tid == 0) {
            __threadfence();
            unsigned target = (unsigned)(t + 1);
            unsigned old = atomicAdd(&g_bar_count, 1u);
            if (old == NBLK - 1) {
                *((volatile unsigned*)&g_bar_count) = 0;
                __threadfence();
                g_bar_gen = target;
            } else {
                while ((int)(g_bar_gen - target) < 0) { __nanosleep(32); }
            }
            __threadfence();
        }
        __syncthreads();
    }
}

// ---------- launch ----------
extern "C" void kernel_launch(void* const* d_in, const int* in_sizes, int n_in,
                              void* d_out, int out_size) {
    const float *x = nullptr, *h0 = nullptr, *c0 = nullptr;
    const float *Wx = nullptr, *Wh = nullptr, *bias = nullptr;
    for (int i = 0; i < n_in; i++) {
        const int s = in_sizes[i];
        const float* p = (const float*)d_in[i];
        if      (s == BB * TT * DD) x = p;
        else if (s == DD * G4)      Wx = p;
        else if (s == UU * G4)      Wh = p;
        else if (s == G4)           bias = p;
        else if (s == BB * UU)      { if (!h0) h0 = p; else c0 = p; }
    }

    static bool attr_set = false;
    if (!attr_set) {
        cudaFuncSetAttribute(lstm_persistent,
                             cudaFuncAttributeMaxDynamicSharedMemorySize,
                             (32768 + 2 * 64 * 68 + 64 * 33) * 4);
        attr_set = true;
    }

    float* hbuf = nullptr;
    void *barc = nullptr, *barg = nullptr;
    cudaGetSymbolAddress((void**)&hbuf, g_h);
    cudaGetSymbolAddress(&barc, g_bar_count);
    cudaGetSymbolAddress(&barg, (const void*)&g_bar_gen);

    cudaMemsetAsync(barc, 0, sizeof(unsigned), 0);
    cudaMemsetAsync(barg, 0, sizeof(unsigned), 0);

    init_h<<<(BB * UU + 255) / 256, 256>>>(h0);
    xg_kernel<<<dim3(G4 / 64, (BB * TT) / 64), 128>>>(x, Wx, bias);

    lstm_persistent<<<NBLK, NTHR, (32768 + 2 * 64 * 68 + 64 * 33) * 4>>>(Wh, c0);

    // final h is in buffer 0 (TT even)
    cudaMemcpyAsync(d_out, hbuf, (size_t)BB * UU * sizeof(float), cudaMemcpyDeviceToDevice, 0);
}

// round 4
// speedup vs baseline: 3.2290x; 1.0694x over previous
#include <cuda_runtime.h>
#include <cstdint>
#include <math.h>

#define BB 64
#define TT 512
#define DD 512
#define UU 1024
#define G4 4096   // 4*UU
#define NBLK 128
#define NTHR 256

// Scratch (allocation-free rule: __device__ globals)
__device__ float g_xg[(size_t)TT * NBLK * BB * 32];  // [T][blk][row][g*8+j] = 512MB
__device__ float g_h[2 * BB * UU];                   // ping-pong h (tf32-rounded except final)
__device__ unsigned g_flag[NBLK];                    // per-block completed-step count

// ---------- helpers ----------
__device__ __forceinline__ unsigned f2tf(float x) {
    unsigned r;
    asm volatile("cvt.rna.tf32.f32 %0, %1;" : "=r"(r) : "f"(x));
    return r;
}
__device__ __forceinline__ float tfbits(float x) { return __uint_as_float(f2tf(x)); }
__device__ __forceinline__ unsigned fu(float x) { return __float_as_uint(x); }

__device__ __forceinline__ void mma_tf32(float d[4], const unsigned a[4], unsigned b0, unsigned b1) {
    asm volatile(
        "mma.sync.aligned.m16n8k8.row.col.f32.tf32.tf32.f32 "
        "{%0,%1,%2,%3}, {%4,%5,%6,%7}, {%8,%9}, {%0,%1,%2,%3};"
        : "+f"(d[0]), "+f"(d[1]), "+f"(d[2]), "+f"(d[3])
        : "r"(a[0]), "r"(a[1]), "r"(a[2]), "r"(a[3]), "r"(b0), "r"(b1));
}
__device__ __forceinline__ float sigmoidf_(float z) { return 1.f / (1.f + expf(-z)); }

__device__ __forceinline__ void cp_async16(uint32_t s, const float* g) {
    asm volatile("cp.async.cg.shared.global [%0], [%1], 16;\n" :: "r"(s), "l"(g));
}
#define CP_COMMIT() asm volatile("cp.async.commit_group;\n" ::: "memory")
#define CP_WAIT(N)  asm volatile("cp.async.wait_group %0;\n" :: "n"(N) : "memory")

// ---------- Kernel 1: xg = x @ Wx + b, relayout to [t][blk][row][g*8+j] ----------
__global__ void __launch_bounds__(128) xg_kernel(const float* __restrict__ x,
                                                 const float* __restrict__ Wx,
                                                 const float* __restrict__ bias) {
    __shared__ float As[64][33];
    __shared__ float Bs[32][65];

    const int tid  = threadIdx.x;
    const int w    = tid >> 5;
    const int lane = tid & 31;
    const int gid  = lane >> 2;
    const int tig  = lane & 3;
    const int wm   = w >> 1;
    const int wn   = w & 1;

    const int m0 = blockIdx.y * 64;
    const int c0 = blockIdx.x * 64;

    float acc[2][4][4];
#pragma unroll
    for (int mi = 0; mi < 2; mi++)
#pragma unroll
        for (int ni = 0; ni < 4; ni++)
#pragma unroll
            for (int j = 0; j < 4; j++) acc[mi][ni][j] = 0.f;

    for (int kc = 0; kc < DD; kc += 32) {
#pragma unroll
        for (int i = 0; i < 4; i++) {
            int id  = tid + i * 128;
            int row = id >> 3;
            int k4  = (id & 7) * 4;
            float4 v = *reinterpret_cast<const float4*>(x + (size_t)(m0 + row) * DD + kc + k4);
            As[row][k4 + 0] = tfbits(v.x);
            As[row][k4 + 1] = tfbits(v.y);
            As[row][k4 + 2] = tfbits(v.z);
            As[row][k4 + 3] = tfbits(v.w);
        }
#pragma unroll
        for (int i = 0; i < 4; i++) {
            int id = tid + i * 128;
            int k  = id >> 4;
            int n4 = (id & 15) * 4;
            float4 v = *reinterpret_cast<const float4*>(Wx + (size_t)(kc + k) * G4 + c0 + n4);
            Bs[k][n4 + 0] = tfbits(v.x);
            Bs[k][n4 + 1] = tfbits(v.y);
            Bs[k][n4 + 2] = tfbits(v.z);
            Bs[k][n4 + 3] = tfbits(v.w);
        }
        __syncthreads();

#pragma unroll
        for (int q = 0; q < 4; q++) {
            const int kk = q * 8 + tig;
            unsigned a[2][4];
#pragma unroll
            for (int mi = 0; mi < 2; mi++) {
                int r0 = wm * 32 + mi * 16 + gid;
                a[mi][0] = fu(As[r0][kk]);
                a[mi][1] = fu(As[r0 + 8][kk]);
                a[mi][2] = fu(As[r0][kk + 4]);
                a[mi][3] = fu(As[r0 + 8][kk + 4]);
            }
#pragma unroll
            for (int ni = 0; ni < 4; ni++) {
                int cb = wn * 32 + ni * 8 + gid;
                unsigned b0 = fu(Bs[kk][cb]);
                unsigned b1 = fu(Bs[kk + 4][cb]);
#pragma unroll
                for (int mi = 0; mi < 2; mi++) mma_tf32(acc[mi][ni], a[mi], b0, b1);
            }
        }
        __syncthreads();
    }

#pragma unroll
    for (int mi = 0; mi < 2; mi++) {
#pragma unroll
        for (int ni = 0; ni < 4; ni++) {
#pragma unroll
            for (int j = 0; j < 4; j++) {
                int m   = m0 + wm * 32 + mi * 16 + gid + ((j >= 2) ? 8 : 0);
                int col = c0 + wn * 32 + ni * 8 + tig * 2 + (j & 1);
                float v = acc[mi][ni][j] + bias[col];
                int b   = m >> 9;        // batch
                int t   = m & (TT - 1);  // time
                int g   = col >> 10;
                int u   = col & (UU - 1);
                int blk = u >> 3;
                int jj  = u & 7;
                g_xg[(((size_t)t * NBLK + blk) * BB + b) * 32 + g * 8 + jj] = v;
            }
        }
    }
}

// ---------- init: h0 -> g_h buffer0 with tf32 rounding ----------
__global__ void init_h(const float* __restrict__ h0) {
    int i = blockIdx.x * blockDim.x + threadIdx.x;
    if (i < BB * UU) g_h[i] = tfbits(h0[i]);
}

// ---------- persistent LSTM kernel ----------
// 128 blocks x 256 threads, 1 block/SM. Block owns u-cols u0..u0+7, all 4 gates.
// Wh slice SMEM-resident as pre-swizzled tf32 B-fragments. c in registers.
// h ping-pong via global; 3-deep cp.async pipeline; flag-based cross-block sync.
__global__ void __launch_bounds__(NTHR, 1) lstm_persistent(const float* __restrict__ Wh,
                                                           const float* __restrict__ c0) {
    extern __shared__ float smem[];
    float* FB  = smem;                  // 32768 f: B-fragments
    float* HS  = FB + 32768;            // 4 * 64*68 f: h staging, 4 buffers
    float* XGS = HS + 4 * 64 * 68;      // 2048 f: xg slab for this step
    float* GM  = XGS + 2048;            // 64*33 f: gate exchange

    const int tid  = threadIdx.x;
    const int w    = tid >> 5;
    const int lane = tid & 31;
    const int gid  = lane >> 2;
    const int tig  = lane & 3;
    const int wm   = w & 3;
    const int wn   = w >> 2;
    const int blk  = blockIdx.x;
    const int u0   = blk * 8;

    // ---- one-time: fill Wh fragments (tf32, pre-swizzled) ----
    for (int idx = tid; idx < 32768; idx += NTHR) {
        int e     = idx & 7;
        int ln    = (idx >> 3) & 31;
        int tile  = (idx >> 8) & 3;
        int kcc32 = idx >> 10;
        int q     = e >> 1;
        int pair  = e & 1;
        int lgid  = ln >> 2;
        int ltig  = ln & 3;
        int k     = kcc32 * 32 + q * 8 + ltig + pair * 4;
        FB[idx] = tfbits(Wh[(size_t)k * G4 + tile * UU + u0 + lgid]);
    }

    float creg[2];
#pragma unroll
    for (int i = 0; i < 2; i++) {
        int e = tid + i * NTHR;
        int row = e >> 3, j = e & 7;
        creg[i] = c0[(size_t)row * UU + u0 + j];
    }
    __syncthreads();

    const float4* FB4 = reinterpret_cast<const float4*>(FB);
    const uint32_t hs_base  = (uint32_t)__cvta_generic_to_shared(HS);
    const uint32_t xgs_base = (uint32_t)__cvta_generic_to_shared(XGS);
    const int r0 = wm * 16 + gid;
    const int t0i = wn * 2, t1i = wn * 2 + 1;

    volatile unsigned* vflag = (volatile unsigned*)g_flag;

    for (int t = 0; t < TT; t++) {
        const float* h_in = g_h + (size_t)(t & 1) * BB * UU;
        float* h_out      = g_h + (size_t)((t + 1) & 1) * BB * UU;
        const float* xgt  = g_xg + ((size_t)t * NBLK + blk) * (BB * 32);

        // ---- wait for all producers of h_t ----
        if (t > 0 && tid < NBLK) {
            while (vflag[tid] < (unsigned)t) { }
            __threadfence();  // acquire-ish: order h reads after flag observation
        }
        __syncthreads();      // also protects XGS/HS reuse vs previous step

        float acc0[4] = {0.f, 0.f, 0.f, 0.f};
        float acc1[4] = {0.f, 0.f, 0.f, 0.f};

        // prologue: xg slab + chunks 0..2 (3 groups in flight)
        {
#pragma unroll
            for (int i = 0; i < 2; i++) {
                int id = tid + i * NTHR;          // 0..511 float4s
                cp_async16(xgs_base + (uint32_t)(id * 16), xgt + id * 4);
            }
#pragma unroll
            for (int i = 0; i < 4; i++) {
                int id = tid + i * NTHR;
                int row = id >> 4, kq = id & 15;
                cp_async16(hs_base + (uint32_t)((row * 68 + kq * 4) * 4),
                           h_in + (size_t)row * UU + kq * 4);
            }
            CP_COMMIT();
#pragma unroll
            for (int p = 1; p <= 2; p++) {
#pragma unroll
                for (int i = 0; i < 4; i++) {
                    int id = tid + i * NTHR;
                    int row = id >> 4, kq = id & 15;
                    cp_async16(hs_base + (uint32_t)((p * 4352 + row * 68 + kq * 4) * 4),
                               h_in + (size_t)row * UU + p * 64 + kq * 4);
                }
                CP_COMMIT();
            }
        }

        for (int kcc = 0; kcc < 16; kcc++) {
            CP_WAIT(2);           // chunk kcc's group complete (3-deep pipeline)
            __syncthreads();      // data visibility + buffer (kcc+3)%4 free

            if (kcc + 3 < 16) {
                int c = kcc + 3;
                int buf = c & 3;
#pragma unroll
                for (int i = 0; i < 4; i++) {
                    int id = tid + i * NTHR;
                    int row = id >> 4, kq = id & 15;
                    cp_async16(hs_base + (uint32_t)((buf * 4352 + row * 68 + kq * 4) * 4),
                               h_in + (size_t)row * UU + c * 64 + kq * 4);
                }
            }
            CP_COMMIT();          // empty group at tail keeps CP_WAIT(2) uniform

            const float* hb = HS + (kcc & 3) * 4352;
#pragma unroll
            for (int sub = 0; sub < 2; sub++) {
                const int kcc32 = kcc * 2 + sub;
                float4 bA0 = FB4[((kcc32 * 4 + t0i) * 32 + lane) * 2 + 0];
                float4 bA1 = FB4[((kcc32 * 4 + t0i) * 32 + lane) * 2 + 1];
                float4 bB0 = FB4[((kcc32 * 4 + t1i) * 32 + lane) * 2 + 0];
                float4 bB1 = FB4[((kcc32 * 4 + t1i) * 32 + lane) * 2 + 1];
#pragma unroll
                for (int q = 0; q < 4; q++) {
                    const int kk = sub * 32 + q * 8 + tig;
                    unsigned a[4];
                    a[0] = fu(hb[r0 * 68 + kk]);
                    a[1] = fu(hb[(r0 + 8) * 68 + kk]);
                    a[2] = fu(hb[r0 * 68 + kk + 4]);
                    a[3] = fu(hb[(r0 + 8) * 68 + kk + 4]);
                    unsigned b0a, b1a, b0b, b1b;
                    if (q == 0)      { b0a = fu(bA0.x); b1a = fu(bA0.y); b0b = fu(bB0.x); b1b = fu(bB0.y); }
                    else if (q == 1) { b0a = fu(bA0.z); b1a = fu(bA0.w); b0b = fu(bB0.z); b1b = fu(bB0.w); }
                    else if (q == 2) { b0a = fu(bA1.x); b1a = fu(bA1.y); b0b = fu(bB1.x); b1b = fu(bB1.y); }
                    else             { b0a = fu(bA1.z); b1a = fu(bA1.w); b0b = fu(bB1.z); b1b = fu(bB1.w); }
                    mma_tf32(acc0, a, b0a, b1a);
                    mma_tf32(acc1, a, b0b, b1b);
                }
            }
        }
        __syncthreads();  // all compute done before GM writes

        // gate exchange
#pragma unroll
        for (int j = 0; j < 4; j++) {
            int row = wm * 16 + gid + ((j >> 1) ? 8 : 0);
            GM[row * 33 + t0i * 8 + tig * 2 + (j & 1)] = acc0[j];
            GM[row * 33 + t1i * 8 + tig * 2 + (j & 1)] = acc1[j];
        }
        __syncthreads();

        // epilogue: gates + c/h update (xg from SMEM)
#pragma unroll
        for (int i = 0; i < 2; i++) {
            int e = tid + i * NTHR;
            int row = e >> 3, j = e & 7;
            float zi = GM[row * 33 + 0 * 8 + j] + XGS[row * 32 + 0 * 8 + j];
            float zf = GM[row * 33 + 1 * 8 + j] + XGS[row * 32 + 1 * 8 + j];
            float zg = GM[row * 33 + 2 * 8 + j] + XGS[row * 32 + 2 * 8 + j];
            float zo = GM[row * 33 + 3 * 8 + j] + XGS[row * 32 + 3 * 8 + j];

            float ig = sigmoidf_(zi);
            float fg = sigmoidf_(zf);
            float gg = tanhf(zg);
            float og = sigmoidf_(zo);

            creg[i] = fg * creg[i] + ig * gg;
            float hv = og * tanhf(creg[i]);
            h_out[(size_t)row * UU + u0 + j] = (t == TT - 1) ? hv : tfbits(hv);
        }

        // publish completion
        __syncthreads();
        if (tid == 0) {
            __threadfence();
            atomicExch(&g_flag[blk], (unsigned)(t + 1));
        }
    }
}

// ---------- launch ----------
extern "C" void kernel_launch(void* const* d_in, const int* in_sizes, int n_in,
                              void* d_out, int out_size) {
    const float *x = nullptr, *h0 = nullptr, *c0 = nullptr;
    const float *Wx = nullptr, *Wh = nullptr, *bias = nullptr;
    for (int i = 0; i < n_in; i++) {
        const int s = in_sizes[i];
        const float* p = (const float*)d_in[i];
        if      (s == BB * TT * DD) x = p;
        else if (s == DD * G4)      Wx = p;
        else if (s == UU * G4)      Wh = p;
        else if (s == G4)           bias = p;
        else if (s == BB * UU)      { if (!h0) h0 = p; else c0 = p; }
    }

    const int SMEM_BYTES = (32768 + 4 * 64 * 68 + 2048 + 64 * 33) * 4;

    static bool attr_set = false;
    if (!attr_set) {
        cudaFuncSetAttribute(lstm_persistent,
                             cudaFuncAttributeMaxDynamicSharedMemorySize, SMEM_BYTES);
        attr_set = true;
    }

    float* hbuf = nullptr;
    void* flg = nullptr;
    cudaGetSymbolAddress((void**)&hbuf, g_h);
    cudaGetSymbolAddress(&flg, g_flag);

    cudaMemsetAsync(flg, 0, NBLK * sizeof(unsigned), 0);

    init_h<<<(BB * UU + 255) / 256, 256>>>(h0);
    xg_kernel<<<dim3(G4 / 64, (BB * TT) / 64), 128>>>(x, Wx, bias);

    lstm_persistent<<<NBLK, NTHR, SMEM_BYTES>>>(Wh, c0);

    // final h is in buffer 0 (TT even)
    cudaMemcpyAsync(d_out, hbuf, (size_t)BB * UU * sizeof(float), cudaMemcpyDeviceToDevice, 0);
}